// round 2
// baseline (speedup 1.0000x reference)
#include <cuda_runtime.h>
#include <cstdint>
#include <cstddef>

#define DM 1024
#define NH 16
#define DK 64
#define BB 8
#define LL 1024
#define MROWS (BB*LL)

#define ATTN_OFF ((size_t)BB*LL*DM)
#define OH_OFF   (ATTN_OFF + (size_t)NH*BB*LL*LL)
#define FULL_OUT 150994944

__device__ float g_qs[(size_t)NH*BB*LL*DK];
__device__ float g_ks[(size_t)NH*BB*LL*DK];
__device__ float g_vs[(size_t)NH*BB*LL*DK];
__device__ float g_hidden[(size_t)BB*LL*DM];
__device__ float g_res[(size_t)BB*LL*DM];
__device__ unsigned char g_mask8[(size_t)BB*LL*LL];
__device__ int g_mask_mode;

__device__ __forceinline__ unsigned f2tf(float x) {
    unsigned u;
    asm("cvt.rna.tf32.f32 %0, %1;" : "=r"(u) : "f"(x));
    return u;
}

__device__ __forceinline__ void mma_tf32(float& c0, float& c1, float& c2, float& c3,
                                         unsigned a0, unsigned a1, unsigned a2, unsigned a3,
                                         unsigned b0, unsigned b1) {
    asm volatile("mma.sync.aligned.m16n8k8.row.col.f32.tf32.tf32.f32 "
        "{%0,%1,%2,%3}, {%4,%5,%6,%7}, {%8,%9}, {%0,%1,%2,%3};\n"
        : "+f"(c0), "+f"(c1), "+f"(c2), "+f"(c3)
        : "r"(a0), "r"(a1), "r"(a2), "r"(a3), "r"(b0), "r"(b1));
}

// mask dtype detection: bool8 / int32 / float32 (0.0/1.0)
__global__ void detect_mask_kernel(const unsigned char* __restrict__ m) {
    __shared__ int s0, sx;
    if (threadIdx.x == 0) { s0 = 0; sx = 0; }
    __syncthreads();
    int o0 = 0, ox = 0;
    for (int i = threadIdx.x; i < 16384; i += 256) {
        int v = m[i];
        if ((i & 3) == 0) o0 |= v; else ox |= v;
    }
    atomicOr(&s0, o0); atomicOr(&sx, ox);
    __syncthreads();
    if (threadIdx.x == 0)
        g_mask_mode = (sx == 0) ? 1 : (s0 == 0) ? 2 : 0;
}

__global__ void convert_mask_kernel(const void* __restrict__ mp) {
    size_t i = (size_t)blockIdx.x * blockDim.x + threadIdx.x;
    if (i >= (size_t)BB*LL*LL) return;
    int mode = g_mask_mode;
    unsigned char r;
    if (mode == 0)      r = (((const unsigned char*)mp)[i] != 0);
    else if (mode == 1) r = (((const int*)mp)[i] != 0);
    else                r = (((const float*)mp)[i] != 0.0f);
    g_mask8[i] = r;
}

// K1: per-head QKV projection: C[8192x64] = X[8192x1024] @ W_h[1024x64]
__global__ __launch_bounds__(256) void qkv_gemm_kernel(
    const float* __restrict__ qi, const float* __restrict__ ki, const float* __restrict__ vi,
    const float* __restrict__ wq, const float* __restrict__ wk, const float* __restrict__ wv)
{
    __shared__ float As[128*36];
    __shared__ float Bs[32*72];
    int z = blockIdx.z;
    int mat = z >> 4, h = z & 15;
    const float* X = (mat == 0) ? qi : (mat == 1) ? ki : vi;
    const float* W = ((mat == 0) ? wq : (mat == 1) ? wk : wv) + (size_t)h * DM * DK;
    float* O = ((mat == 0) ? g_qs : (mat == 1) ? g_ks : g_vs) + (size_t)h * MROWS * DK;

    int tid = threadIdx.x;
    int w = tid >> 5, lane = tid & 31;
    int g = lane >> 2, tg = lane & 3;
    int wm = w & 3, wn = w >> 2;
    int m0 = blockIdx.x * 128;

    float c[2][4][4];
    #pragma unroll
    for (int a = 0; a < 2; a++)
        #pragma unroll
        for (int b = 0; b < 4; b++)
            #pragma unroll
            for (int d = 0; d < 4; d++) c[a][b][d] = 0.f;

    for (int k0 = 0; k0 < DM; k0 += 32) {
        #pragma unroll
        for (int i = 0; i < 4; i++) {
            int idx = tid + i * 256;
            int r = idx >> 3, c4 = idx & 7;
            *(float4*)(As + r * 36 + c4 * 4) =
                *(const float4*)(X + (size_t)(m0 + r) * DM + k0 + c4 * 4);
        }
        #pragma unroll
        for (int i = 0; i < 2; i++) {
            int idx = tid + i * 256;
            int r = idx >> 4, c4 = idx & 15;
            *(float4*)(Bs + r * 72 + c4 * 4) =
                *(const float4*)(W + (size_t)(k0 + r) * DK + c4 * 4);
        }
        __syncthreads();
        #pragma unroll
        for (int kk = 0; kk < 4; kk++) {
            unsigned a[2][4];
            #pragma unroll
            for (int mi = 0; mi < 2; mi++) {
                int rb = wm * 32 + mi * 16;
                a[mi][0] = f2tf(As[(rb + g) * 36 + kk * 8 + tg]);
                a[mi][1] = f2tf(As[(rb + g + 8) * 36 + kk * 8 + tg]);
                a[mi][2] = f2tf(As[(rb + g) * 36 + kk * 8 + tg + 4]);
                a[mi][3] = f2tf(As[(rb + g + 8) * 36 + kk * 8 + tg + 4]);
            }
            #pragma unroll
            for (int ni = 0; ni < 4; ni++) {
                unsigned b0 = __float_as_uint(Bs[(kk * 8 + tg) * 72 + wn * 32 + ni * 8 + g]);
                unsigned b1 = __float_as_uint(Bs[(kk * 8 + tg + 4) * 72 + wn * 32 + ni * 8 + g]);
                #pragma unroll
                for (int mi = 0; mi < 2; mi++)
                    mma_tf32(c[mi][ni][0], c[mi][ni][1], c[mi][ni][2], c[mi][ni][3],
                             a[mi][0], a[mi][1], a[mi][2], a[mi][3], b0, b1);
            }
        }
        __syncthreads();
    }
    #pragma unroll
    for (int mi = 0; mi < 2; mi++)
        #pragma unroll
        for (int ni = 0; ni < 4; ni++) {
            int row = m0 + wm * 32 + mi * 16 + g;
            int col = wn * 32 + ni * 8 + 2 * tg;
            *(float2*)(O + (size_t)row * DK + col)       = make_float2(c[mi][ni][0], c[mi][ni][1]);
            *(float2*)(O + (size_t)(row + 8) * DK + col) = make_float2(c[mi][ni][2], c[mi][ni][3]);
        }
}

// K2: fused attention, two-pass softmax (scores bounded -> no max)
__global__ __launch_bounds__(256) void attn_kernel(float* __restrict__ out, int full)
{
    __shared__ float Ks[64*68];
    __shared__ float Vs[64*68];
    int hb = blockIdx.y;
    int h = hb >> 3, b = hb & 7;
    int tid = threadIdx.x;
    int w = tid >> 5, lane = tid & 31;
    int g = lane >> 2, tg = lane & 3;
    int qb = blockIdx.x * 128 + w * 16;
    const float* Qp = g_qs + (size_t)hb * LL * DK;
    const float* Kp = g_ks + (size_t)hb * LL * DK;
    const float* Vp = g_vs + (size_t)hb * LL * DK;
    const unsigned char* Mp = g_mask8 + ((size_t)b * LL + qb) * LL;

    unsigned aq[8][4];
    #pragma unroll
    for (int kk = 0; kk < 8; kk++) {
        aq[kk][0] = f2tf(Qp[(size_t)(qb + g) * DK + kk * 8 + tg]);
        aq[kk][1] = f2tf(Qp[(size_t)(qb + g + 8) * DK + kk * 8 + tg]);
        aq[kk][2] = f2tf(Qp[(size_t)(qb + g) * DK + kk * 8 + tg + 4]);
        aq[kk][3] = f2tf(Qp[(size_t)(qb + g + 8) * DK + kk * 8 + tg + 4]);
    }
    const float invt = 1.0f / 32.0f;  // 1/sqrt(D_MODEL)
    float rs0 = 0.f, rs1 = 0.f;

    for (int kt = 0; kt < 16; kt++) {
        __syncthreads();
        #pragma unroll
        for (int i = 0; i < 4; i++) {
            int idx = tid + i * 256;
            int r = idx >> 4, c4 = idx & 15;
            *(float4*)(Ks + r * 68 + c4 * 4) =
                *(const float4*)(Kp + (size_t)(kt * 64 + r) * DK + c4 * 4);
        }
        __syncthreads();
        #pragma unroll
        for (int nt = 0; nt < 8; nt++) {
            float c0 = 0, c1 = 0, c2 = 0, c3 = 0;
            #pragma unroll
            for (int kk = 0; kk < 8; kk++) {
                unsigned b0 = __float_as_uint(Ks[(nt * 8 + g) * 68 + kk * 8 + tg]);
                unsigned b1 = __float_as_uint(Ks[(nt * 8 + g) * 68 + kk * 8 + tg + 4]);
                mma_tf32(c0, c1, c2, c3, aq[kk][0], aq[kk][1], aq[kk][2], aq[kk][3], b0, b1);
            }
            int key = kt * 64 + nt * 8 + 2 * tg;
            uchar2 m0 = *(const uchar2*)(Mp + (size_t)g * LL + key);
            uchar2 m1 = *(const uchar2*)(Mp + (size_t)(g + 8) * LL + key);
            rs0 += (m0.x ? 0.f : __expf(c0 * invt)) + (m0.y ? 0.f : __expf(c1 * invt));
            rs1 += (m1.x ? 0.f : __expf(c2 * invt)) + (m1.y ? 0.f : __expf(c3 * invt));
        }
    }
    rs0 += __shfl_xor_sync(0xffffffffu, rs0, 1);
    rs0 += __shfl_xor_sync(0xffffffffu, rs0, 2);
    rs1 += __shfl_xor_sync(0xffffffffu, rs1, 1);
    rs1 += __shfl_xor_sync(0xffffffffu, rs1, 2);
    float inv0 = 1.f / rs0, inv1 = 1.f / rs1;

    float oac[8][4];
    #pragma unroll
    for (int vt = 0; vt < 8; vt++)
        #pragma unroll
        for (int j = 0; j < 4; j++) oac[vt][j] = 0.f;

    float* attnp = out + ATTN_OFF + ((size_t)hb * LL + qb) * LL;
    bool doOh = full && (b == 0) && ((h & 1) == 0);
    float* ohp = out + OH_OFF + ((size_t)(h >> 1) * LL + qb) * LL;

    for (int kt = 0; kt < 16; kt++) {
        __syncthreads();
        #pragma unroll
        for (int i = 0; i < 4; i++) {
            int idx = tid + i * 256;
            int r = idx >> 4, c4 = idx & 15;
            *(float4*)(Ks + r * 68 + c4 * 4) =
                *(const float4*)(Kp + (size_t)(kt * 64 + r) * DK + c4 * 4);
            *(float4*)(Vs + r * 68 + c4 * 4) =
                *(const float4*)(Vp + (size_t)(kt * 64 + r) * DK + c4 * 4);
        }
        __syncthreads();
        float p[8][4];
        #pragma unroll
        for (int nt = 0; nt < 8; nt++) {
            float c0 = 0, c1 = 0, c2 = 0, c3 = 0;
            #pragma unroll
            for (int kk = 0; kk < 8; kk++) {
                unsigned b0 = __float_as_uint(Ks[(nt * 8 + g) * 68 + kk * 8 + tg]);
                unsigned b1 = __float_as_uint(Ks[(nt * 8 + g) * 68 + kk * 8 + tg + 4]);
                mma_tf32(c0, c1, c2, c3, aq[kk][0], aq[kk][1], aq[kk][2], aq[kk][3], b0, b1);
            }
            int key = kt * 64 + nt * 8 + 2 * tg;
            uchar2 m0 = *(const uchar2*)(Mp + (size_t)g * LL + key);
            uchar2 m1 = *(const uchar2*)(Mp + (size_t)(g + 8) * LL + key);
            float p0 = m0.x ? 0.f : __expf(c0 * invt) * inv0;
            float p1 = m0.y ? 0.f : __expf(c1 * invt) * inv0;
            float p2 = m1.x ? 0.f : __expf(c2 * invt) * inv1;
            float p3 = m1.y ? 0.f : __expf(c3 * invt) * inv1;
            if (full) {
                *(float2*)(attnp + (size_t)g * LL + key)       = make_float2(p0, p1);
                *(float2*)(attnp + (size_t)(g + 8) * LL + key) = make_float2(p2, p3);
                if (doOh) {
                    *(float2*)(ohp + (size_t)g * LL + key)       = make_float2(p0, p1);
                    *(float2*)(ohp + (size_t)(g + 8) * LL + key) = make_float2(p2, p3);
                }
            }
            p[nt][0] = __uint_as_float(f2tf(p0));
            p[nt][1] = __uint_as_float(f2tf(p1));
            p[nt][2] = __uint_as_float(f2tf(p2));
            p[nt][3] = __uint_as_float(f2tf(p3));
        }
        // P@V with key permutation pi=[0,2,4,6,1,3,5,7]; C-frag reused as A-frag
        #pragma unroll
        for (int vt = 0; vt < 8; vt++) {
            #pragma unroll
            for (int kk2 = 0; kk2 < 8; kk2++) {
                unsigned b0 = __float_as_uint(Vs[(kk2 * 8 + 2 * tg) * 68 + vt * 8 + g]);
                unsigned b1 = __float_as_uint(Vs[(kk2 * 8 + 2 * tg + 1) * 68 + vt * 8 + g]);
                mma_tf32(oac[vt][0], oac[vt][1], oac[vt][2], oac[vt][3],
                         __float_as_uint(p[kk2][0]), __float_as_uint(p[kk2][2]),
                         __float_as_uint(p[kk2][1]), __float_as_uint(p[kk2][3]),
                         b0, b1);
            }
        }
    }
    #pragma unroll
    for (int vt = 0; vt < 8; vt++) {
        int dv = vt * 8 + 2 * tg;
        int r0 = qb + g, r1 = qb + g + 8;
        *(float2*)(g_hidden + ((size_t)b * LL + r0) * DM + h * DK + dv) =
            make_float2(oac[vt][0], oac[vt][1]);
        *(float2*)(g_hidden + ((size_t)b * LL + r1) * DM + h * DK + dv) =
            make_float2(oac[vt][2], oac[vt][3]);
    }
}

// K3: out-proj + bias + residual: res = hidden @ proj_w^T + pb + q
__global__ __launch_bounds__(256) void proj_gemm_kernel(
    const float* __restrict__ qin, const float* __restrict__ pw, const float* __restrict__ pb)
{
    __shared__ float As[128*36];
    __shared__ float Bs[32*76];
    int n0 = blockIdx.y * 64;
    int m0 = blockIdx.x * 128;
    int tid = threadIdx.x;
    int w = tid >> 5, lane = tid & 31;
    int g = lane >> 2, tg = lane & 3;
    int wm = w & 3, wn = w >> 2;

    float c[2][4][4];
    #pragma unroll
    for (int a = 0; a < 2; a++)
        #pragma unroll
        for (int b = 0; b < 4; b++)
            #pragma unroll
            for (int d = 0; d < 4; d++) c[a][b][d] = 0.f;

    for (int k0 = 0; k0 < DM; k0 += 32) {
        #pragma unroll
        for (int i = 0; i < 4; i++) {
            int idx = tid + i * 256;
            int r = idx >> 3, c4 = idx & 7;
            *(float4*)(As + r * 36 + c4 * 4) =
                *(const float4*)(g_hidden + (size_t)(m0 + r) * DM + k0 + c4 * 4);
        }
        #pragma unroll
        for (int i = 0; i < 2; i++) {
            int idx = tid + i * 256;
            int j = idx >> 3, c4 = idx & 7;
            float4 vb = *(const float4*)(pw + (size_t)(n0 + j) * DM + k0 + c4 * 4);
            Bs[(c4 * 4 + 0) * 76 + j] = vb.x;
            Bs[(c4 * 4 + 1) * 76 + j] = vb.y;
            Bs[(c4 * 4 + 2) * 76 + j] = vb.z;
            Bs[(c4 * 4 + 3) * 76 + j] = vb.w;
        }
        __syncthreads();
        #pragma unroll
        for (int kk = 0; kk < 4; kk++) {
            unsigned a[2][4];
            #pragma unroll
            for (int mi = 0; mi < 2; mi++) {
                int rb = wm * 32 + mi * 16;
                a[mi][0] = f2tf(As[(rb + g) * 36 + kk * 8 + tg]);
                a[mi][1] = f2tf(As[(rb + g + 8) * 36 + kk * 8 + tg]);
                a[mi][2] = f2tf(As[(rb + g) * 36 + kk * 8 + tg + 4]);
                a[mi][3] = f2tf(As[(rb + g + 8) * 36 + kk * 8 + tg + 4]);
            }
            #pragma unroll
            for (int ni = 0; ni < 4; ni++) {
                unsigned b0 = __float_as_uint(Bs[(kk * 8 + tg) * 76 + wn * 32 + ni * 8 + g]);
                unsigned b1 = __float_as_uint(Bs[(kk * 8 + tg + 4) * 76 + wn * 32 + ni * 8 + g]);
                #pragma unroll
                for (int mi = 0; mi < 2; mi++)
                    mma_tf32(c[mi][ni][0], c[mi][ni][1], c[mi][ni][2], c[mi][ni][3],
                             a[mi][0], a[mi][1], a[mi][2], a[mi][3], b0, b1);
            }
        }
        __syncthreads();
    }
    #pragma unroll
    for (int mi = 0; mi < 2; mi++)
        #pragma unroll
        for (int ni = 0; ni < 4; ni++) {
            int row = m0 + wm * 32 + mi * 16 + g;
            int col = n0 + wn * 32 + ni * 8 + 2 * tg;
            float b0v = pb[col], b1v = pb[col + 1];
            g_res[(size_t)row * DM + col]     = c[mi][ni][0] + b0v + qin[(size_t)row * DM + col];
            g_res[(size_t)row * DM + col + 1] = c[mi][ni][1] + b1v + qin[(size_t)row * DM + col + 1];
            g_res[(size_t)(row + 8) * DM + col]     = c[mi][ni][2] + b0v + qin[(size_t)(row + 8) * DM + col];
            g_res[(size_t)(row + 8) * DM + col + 1] = c[mi][ni][3] + b1v + qin[(size_t)(row + 8) * DM + col + 1];
        }
}

// K4: LayerNorm
__global__ __launch_bounds__(256) void ln_kernel(const float* __restrict__ gma,
                                                 const float* __restrict__ bta,
                                                 float* __restrict__ out)
{
    int r = blockIdx.x, tid = threadIdx.x;
    const float* x = g_res + (size_t)r * DM;
    float4 xv = *(const float4*)(x + tid * 4);
    float s  = xv.x + xv.y + xv.z + xv.w;
    float sq = xv.x * xv.x + xv.y * xv.y + xv.z * xv.z + xv.w * xv.w;
    #pragma unroll
    for (int o = 16; o > 0; o >>= 1) {
        s  += __shfl_xor_sync(0xffffffffu, s, o);
        sq += __shfl_xor_sync(0xffffffffu, sq, o);
    }
    __shared__ float ss[8], ssq[8];
    int w = tid >> 5;
    if ((tid & 31) == 0) { ss[w] = s; ssq[w] = sq; }
    __syncthreads();
    if (tid < 32) {
        s  = (tid < 8) ? ss[tid]  : 0.f;
        sq = (tid < 8) ? ssq[tid] : 0.f;
        #pragma unroll
        for (int o = 4; o > 0; o >>= 1) {
            s  += __shfl_xor_sync(0xffffffffu, s, o);
            sq += __shfl_xor_sync(0xffffffffu, sq, o);
        }
        if (tid == 0) { ss[0] = s; ssq[0] = sq; }
    }
    __syncthreads();
    float mu   = ss[0] * (1.f / 1024.f);
    float var  = ssq[0] * (1.f / 1024.f) - mu * mu;
    float rstd = rsqrtf(var + 1e-6f);
    float4 gv = *(const float4*)(gma + tid * 4);
    float4 bv = *(const float4*)(bta + tid * 4);
    float4 o;
    o.x = (xv.x - mu) * rstd * gv.x + bv.x;
    o.y = (xv.y - mu) * rstd * gv.y + bv.y;
    o.z = (xv.z - mu) * rstd * gv.z + bv.z;
    o.w = (xv.w - mu) * rstd * gv.w + bv.w;
    *(float4*)(out + (size_t)r * DM + tid * 4) = o;
}

extern "C" void kernel_launch(void* const* d_in, const int* in_sizes, int n_in,
                              void* d_out, int out_size) {
    const float* q  = (const float*)d_in[0];
    const float* k  = (const float*)d_in[1];
    const float* v  = (const float*)d_in[2];
    const void*  mk = d_in[3];
    const float* wq = (const float*)d_in[4];
    const float* wk = (const float*)d_in[5];
    const float* wv = (const float*)d_in[6];
    const float* pw = (const float*)d_in[7];
    const float* pb = (const float*)d_in[8];
    const float* lg = (const float*)d_in[9];
    const float* lb = (const float*)d_in[10];
    float* out = (float*)d_out;
    int full = (out_size >= (int)FULL_OUT) ? 1 : 0;

    detect_mask_kernel<<<1, 256>>>((const unsigned char*)mk);
    convert_mask_kernel<<<32768, 256>>>(mk);
    dim3 gq(64, 1, 48);
    qkv_gemm_kernel<<<gq, 256>>>(q, k, v, wq, wk, wv);
    dim3 ga(8, 128);
    attn_kernel<<<ga, 256>>>(out, full);
    dim3 gp(64, 16);
    proj_gemm_kernel<<<gp, 256>>>(q, pw, pb);
    ln_kernel<<<MROWS, 256>>>(lg, lb, out);
}

// round 3
// speedup vs baseline: 1.1413x; 1.1413x over previous
#include <cuda_runtime.h>
#include <cstdint>
#include <cstddef>

#define DM 1024
#define NH 16
#define DK 64
#define BB 8
#define LL 1024
#define MROWS (BB*LL)

#define ATTN_OFF ((size_t)BB*LL*DM)
#define OH_OFF   (ATTN_OFF + (size_t)NH*BB*LL*LL)
#define FULL_OUT 150994944

__device__ float g_qs[(size_t)NH*BB*LL*DK];
__device__ float g_ks[(size_t)NH*BB*LL*DK];
__device__ float g_vs[(size_t)NH*BB*LL*DK];
__device__ float g_hidden[(size_t)BB*LL*DM];
__device__ float g_res[(size_t)BB*LL*DM];
__device__ float g_inv[(size_t)NH*BB*LL];
__device__ unsigned char g_mask8[(size_t)BB*LL*LL];
__device__ int g_mask_mode;

__device__ __forceinline__ unsigned f2tf(float x) {
    unsigned u;
    asm("cvt.rna.tf32.f32 %0, %1;" : "=r"(u) : "f"(x));
    return u;
}

__device__ __forceinline__ void mma_tf32(float& c0, float& c1, float& c2, float& c3,
                                         unsigned a0, unsigned a1, unsigned a2, unsigned a3,
                                         unsigned b0, unsigned b1) {
    asm volatile("mma.sync.aligned.m16n8k8.row.col.f32.tf32.tf32.f32 "
        "{%0,%1,%2,%3}, {%4,%5,%6,%7}, {%8,%9}, {%0,%1,%2,%3};\n"
        : "+f"(c0), "+f"(c1), "+f"(c2), "+f"(c3)
        : "r"(a0), "r"(a1), "r"(a2), "r"(a3), "r"(b0), "r"(b1));
}

__device__ __forceinline__ void cpa16(float* dst, const float* src) {
    unsigned d = (unsigned)__cvta_generic_to_shared(dst);
    asm volatile("cp.async.ca.shared.global [%0], [%1], 16;\n" :: "r"(d), "l"(src));
}
#define CPCOMMIT asm volatile("cp.async.commit_group;\n")
#define CPWAIT1  asm volatile("cp.async.wait_group 1;\n")

// ---------- mask dtype detection: bool8 / int32 / float32 ----------
__global__ void detect_mask_kernel(const unsigned char* __restrict__ m) {
    __shared__ int s0, sx;
    if (threadIdx.x == 0) { s0 = 0; sx = 0; }
    __syncthreads();
    int o0 = 0, ox = 0;
    for (int i = threadIdx.x; i < 16384; i += 256) {
        int v = m[i];
        if ((i & 3) == 0) o0 |= v; else ox |= v;
    }
    atomicOr(&s0, o0); atomicOr(&sx, ox);
    __syncthreads();
    if (threadIdx.x == 0)
        g_mask_mode = (sx == 0) ? 1 : (s0 == 0) ? 2 : 0;
}

__global__ void convert_mask_kernel(const void* __restrict__ mp) {
    size_t i = (size_t)blockIdx.x * blockDim.x + threadIdx.x;
    if (i >= (size_t)BB*LL*LL) return;
    int mode = g_mask_mode;
    unsigned char r;
    if (mode == 0)      r = (((const unsigned char*)mp)[i] != 0);
    else if (mode == 1) r = (((const int*)mp)[i] != 0);
    else                r = (((const float*)mp)[i] != 0.0f);
    g_mask8[i] = r;
}

// ---------- K1: QKV projection, 2-stage cp.async pipeline ----------
__global__ __launch_bounds__(256) void qkv_gemm_kernel(
    const float* __restrict__ qi, const float* __restrict__ ki, const float* __restrict__ vi,
    const float* __restrict__ wq, const float* __restrict__ wk, const float* __restrict__ wv)
{
    extern __shared__ float sm[];
    float* As = sm;                 // 2 stages of 128x36
    float* Bs = sm + 2*128*36;      // 2 stages of 32x72
    int z = blockIdx.z;
    int mat = z >> 4, h = z & 15;
    const float* X = (mat == 0) ? qi : (mat == 1) ? ki : vi;
    const float* W = ((mat == 0) ? wq : (mat == 1) ? wk : wv) + (size_t)h * DM * DK;
    float* O = ((mat == 0) ? g_qs : (mat == 1) ? g_ks : g_vs) + (size_t)h * MROWS * DK;

    int tid = threadIdx.x;
    int w = tid >> 5, lane = tid & 31;
    int g = lane >> 2, tg = lane & 3;
    int wm = w & 3, wn = w >> 2;
    int m0 = blockIdx.x * 128;

    float c[2][4][4];
    #pragma unroll
    for (int a = 0; a < 2; a++)
        #pragma unroll
        for (int b = 0; b < 4; b++)
            #pragma unroll
            for (int d = 0; d < 4; d++) c[a][b][d] = 0.f;

    auto loadTile = [&](int stage, int it) {
        int k0 = it * 32;
        float* Ad = As + stage * (128*36);
        float* Bd = Bs + stage * (32*72);
        #pragma unroll
        for (int i = 0; i < 4; i++) {
            int idx = tid + i * 256;
            int r = idx >> 3, c4 = idx & 7;
            cpa16(Ad + r * 36 + c4 * 4, X + (size_t)(m0 + r) * DM + k0 + c4 * 4);
        }
        #pragma unroll
        for (int i = 0; i < 2; i++) {
            int idx = tid + i * 256;
            int r = idx >> 4, c4 = idx & 15;
            cpa16(Bd + r * 72 + c4 * 4, W + (size_t)(k0 + r) * DK + c4 * 4);
        }
    };

    loadTile(0, 0); CPCOMMIT;
    loadTile(1, 1); CPCOMMIT;

    for (int it = 0; it < 32; it++) {
        CPWAIT1;
        __syncthreads();
        const float* A_ = As + (it & 1) * (128*36);
        const float* B_ = Bs + (it & 1) * (32*72);
        #pragma unroll
        for (int kk = 0; kk < 4; kk++) {
            unsigned a[2][4];
            #pragma unroll
            for (int mi = 0; mi < 2; mi++) {
                int rb = wm * 32 + mi * 16;
                a[mi][0] = f2tf(A_[(rb + g) * 36 + kk * 8 + tg]);
                a[mi][1] = f2tf(A_[(rb + g + 8) * 36 + kk * 8 + tg]);
                a[mi][2] = f2tf(A_[(rb + g) * 36 + kk * 8 + tg + 4]);
                a[mi][3] = f2tf(A_[(rb + g + 8) * 36 + kk * 8 + tg + 4]);
            }
            #pragma unroll
            for (int ni = 0; ni < 4; ni++) {
                unsigned b0 = __float_as_uint(B_[(kk * 8 + tg) * 72 + wn * 32 + ni * 8 + g]);
                unsigned b1 = __float_as_uint(B_[(kk * 8 + tg + 4) * 72 + wn * 32 + ni * 8 + g]);
                #pragma unroll
                for (int mi = 0; mi < 2; mi++)
                    mma_tf32(c[mi][ni][0], c[mi][ni][1], c[mi][ni][2], c[mi][ni][3],
                             a[mi][0], a[mi][1], a[mi][2], a[mi][3], b0, b1);
            }
        }
        __syncthreads();
        if (it + 2 < 32) loadTile(it & 1, it + 2);
        CPCOMMIT;
    }
    #pragma unroll
    for (int mi = 0; mi < 2; mi++)
        #pragma unroll
        for (int ni = 0; ni < 4; ni++) {
            int row = m0 + wm * 32 + mi * 16 + g;
            int col = wn * 32 + ni * 8 + 2 * tg;
            *(float2*)(O + (size_t)row * DK + col)       = make_float2(c[mi][ni][0], c[mi][ni][1]);
            *(float2*)(O + (size_t)(row + 8) * DK + col) = make_float2(c[mi][ni][2], c[mi][ni][3]);
        }
}

// ---------- K2a: scores -> exp -> unnormalized E + row-sum inverses ----------
__global__ __launch_bounds__(256) void score_kernel(float* __restrict__ out)
{
    __shared__ float Ks[64*68];
    int hb = blockIdx.y;
    int b = hb & 7;
    int tid = threadIdx.x;
    int w = tid >> 5, lane = tid & 31;
    int g = lane >> 2, tg = lane & 3;
    int qb = blockIdx.x * 128 + w * 16;
    const float* Qp = g_qs + (size_t)hb * LL * DK;
    const float* Kp = g_ks + (size_t)hb * LL * DK;
    const unsigned char* Mp = g_mask8 + ((size_t)b * LL + qb) * LL;
    float* Ep = out + ATTN_OFF + ((size_t)hb * LL + qb) * LL;

    unsigned aq[8][4];
    #pragma unroll
    for (int kk = 0; kk < 8; kk++) {
        aq[kk][0] = f2tf(Qp[(size_t)(qb + g) * DK + kk * 8 + tg]);
        aq[kk][1] = f2tf(Qp[(size_t)(qb + g + 8) * DK + kk * 8 + tg]);
        aq[kk][2] = f2tf(Qp[(size_t)(qb + g) * DK + kk * 8 + tg + 4]);
        aq[kk][3] = f2tf(Qp[(size_t)(qb + g + 8) * DK + kk * 8 + tg + 4]);
    }
    const float invt = 1.0f / 32.0f;   // 1/sqrt(D_MODEL)
    float rs0 = 0.f, rs1 = 0.f;

    for (int kt = 0; kt < 16; kt++) {
        __syncthreads();
        #pragma unroll
        for (int i = 0; i < 4; i++) {
            int idx = tid + i * 256;
            int r = idx >> 4, c4 = idx & 15;
            *(float4*)(Ks + r * 68 + c4 * 4) =
                *(const float4*)(Kp + (size_t)(kt * 64 + r) * DK + c4 * 4);
        }
        __syncthreads();
        #pragma unroll
        for (int nt = 0; nt < 8; nt++) {
            float c0 = 0, c1 = 0, c2 = 0, c3 = 0;
            #pragma unroll
            for (int kk = 0; kk < 8; kk++) {
                unsigned b0 = __float_as_uint(Ks[(nt * 8 + g) * 68 + kk * 8 + tg]);
                unsigned b1 = __float_as_uint(Ks[(nt * 8 + g) * 68 + kk * 8 + tg + 4]);
                mma_tf32(c0, c1, c2, c3, aq[kk][0], aq[kk][1], aq[kk][2], aq[kk][3], b0, b1);
            }
            int key = kt * 64 + nt * 8 + 2 * tg;
            uchar2 m0 = *(const uchar2*)(Mp + (size_t)g * LL + key);
            uchar2 m1 = *(const uchar2*)(Mp + (size_t)(g + 8) * LL + key);
            float p0 = m0.x ? 0.f : __expf(c0 * invt);
            float p1 = m0.y ? 0.f : __expf(c1 * invt);
            float p2 = m1.x ? 0.f : __expf(c2 * invt);
            float p3 = m1.y ? 0.f : __expf(c3 * invt);
            rs0 += p0 + p1; rs1 += p2 + p3;
            *(float2*)(Ep + (size_t)g * LL + key)       = make_float2(p0, p1);
            *(float2*)(Ep + (size_t)(g + 8) * LL + key) = make_float2(p2, p3);
        }
    }
    rs0 += __shfl_xor_sync(0xffffffffu, rs0, 1);
    rs0 += __shfl_xor_sync(0xffffffffu, rs0, 2);
    rs1 += __shfl_xor_sync(0xffffffffu, rs1, 1);
    rs1 += __shfl_xor_sync(0xffffffffu, rs1, 2);
    if (tg == 0) {
        g_inv[(size_t)hb * LL + qb + g]     = 1.f / rs0;
        g_inv[(size_t)hb * LL + qb + g + 8] = 1.f / rs1;
    }
}

// ---------- K2b: normalize E in place (+one_head) and O = P @ V ----------
__global__ __launch_bounds__(256) void pv_kernel(float* __restrict__ out, int full)
{
    extern __shared__ float sm[];
    float* Ps   = sm;               // 128 x 68
    float* Vs   = sm + 128*68;      // 64 x 68
    float* sInv = Vs + 64*68;       // 128
    int hb = blockIdx.y;
    int h = hb >> 3, b = hb & 7;
    int tid = threadIdx.x;
    int w = tid >> 5, lane = tid & 31;
    int g = lane >> 2, tg = lane & 3;
    int qb0 = blockIdx.x * 128;
    int wr = w * 16;
    const float* Vp = g_vs + (size_t)hb * LL * DK;
    float* Ep = out + ATTN_OFF + ((size_t)hb * LL + qb0) * LL;
    bool doOh = full && (b == 0) && ((h & 1) == 0);
    float* ohp = out + OH_OFF + ((size_t)(h >> 1) * LL + qb0) * LL;

    if (tid < 128) sInv[tid] = g_inv[(size_t)hb * LL + qb0 + tid];

    float oac[8][4];
    #pragma unroll
    for (int vt = 0; vt < 8; vt++)
        #pragma unroll
        for (int j = 0; j < 4; j++) oac[vt][j] = 0.f;

    for (int kt = 0; kt < 16; kt++) {
        __syncthreads();
        #pragma unroll
        for (int i = 0; i < 4; i++) {
            int idx = tid + i * 256;
            int key = idx >> 4, c4 = idx & 15;
            *(float4*)(Vs + key * 68 + c4 * 4) =
                *(const float4*)(Vp + (size_t)(kt * 64 + key) * DK + c4 * 4);
        }
        #pragma unroll
        for (int i = 0; i < 8; i++) {
            int idx = tid + i * 256;
            int row = idx >> 4, c4 = idx & 15;
            float4 e = *(const float4*)(Ep + (size_t)row * LL + kt * 64 + c4 * 4);
            float iv = sInv[row];
            e.x *= iv; e.y *= iv; e.z *= iv; e.w *= iv;
            *(float4*)(Ep + (size_t)row * LL + kt * 64 + c4 * 4) = e;
            if (doOh)
                *(float4*)(ohp + (size_t)row * LL + kt * 64 + c4 * 4) = e;
            float4 t;
            t.x = __uint_as_float(f2tf(e.x));
            t.y = __uint_as_float(f2tf(e.y));
            t.z = __uint_as_float(f2tf(e.z));
            t.w = __uint_as_float(f2tf(e.w));
            *(float4*)(Ps + row * 68 + c4 * 4) = t;
        }
        __syncthreads();
        // PV: logical key order pi = [0,2,4,6,1,3,5,7] on both A and B -> identity product
        #pragma unroll
        for (int kk = 0; kk < 8; kk++) {
            unsigned a0 = __float_as_uint(Ps[(wr + g) * 68 + kk * 8 + 2 * tg]);
            unsigned a1 = __float_as_uint(Ps[(wr + g + 8) * 68 + kk * 8 + 2 * tg]);
            unsigned a2 = __float_as_uint(Ps[(wr + g) * 68 + kk * 8 + 2 * tg + 1]);
            unsigned a3 = __float_as_uint(Ps[(wr + g + 8) * 68 + kk * 8 + 2 * tg + 1]);
            #pragma unroll
            for (int vt = 0; vt < 8; vt++) {
                unsigned b0 = __float_as_uint(Vs[(kk * 8 + 2 * tg) * 68 + vt * 8 + g]);
                unsigned b1 = __float_as_uint(Vs[(kk * 8 + 2 * tg + 1) * 68 + vt * 8 + g]);
                mma_tf32(oac[vt][0], oac[vt][1], oac[vt][2], oac[vt][3],
                         a0, a1, a2, a3, b0, b1);
            }
        }
    }
    #pragma unroll
    for (int vt = 0; vt < 8; vt++) {
        int dv = vt * 8 + 2 * tg;
        int r0 = qb0 + wr + g, r1 = qb0 + wr + g + 8;
        *(float2*)(g_hidden + ((size_t)b * LL + r0) * DM + h * DK + dv) =
            make_float2(oac[vt][0], oac[vt][1]);
        *(float2*)(g_hidden + ((size_t)b * LL + r1) * DM + h * DK + dv) =
            make_float2(oac[vt][2], oac[vt][3]);
    }
}

// ---------- K3: out-proj + bias + residual, 2-stage cp.async ----------
__global__ __launch_bounds__(256) void proj_gemm_kernel(
    const float* __restrict__ qin, const float* __restrict__ pw, const float* __restrict__ pb)
{
    extern __shared__ float sm[];
    float* As = sm;                 // 2 stages of 128x36
    float* Bs = sm + 2*128*36;      // 2 stages of 64x36  (pw rows, already B[k][n] col-major)
    int n0 = blockIdx.y * 64;
    int m0 = blockIdx.x * 128;
    int tid = threadIdx.x;
    int w = tid >> 5, lane = tid & 31;
    int g = lane >> 2, tg = lane & 3;
    int wm = w & 3, wn = w >> 2;

    float c[2][4][4];
    #pragma unroll
    for (int a = 0; a < 2; a++)
        #pragma unroll
        for (int b = 0; b < 4; b++)
            #pragma unroll
            for (int d = 0; d < 4; d++) c[a][b][d] = 0.f;

    auto loadTile = [&](int stage, int it) {
        int k0 = it * 32;
        float* Ad = As + stage * (128*36);
        float* Bd = Bs + stage * (64*36);
        #pragma unroll
        for (int i = 0; i < 4; i++) {
            int idx = tid + i * 256;
            int r = idx >> 3, c4 = idx & 7;
            cpa16(Ad + r * 36 + c4 * 4, g_hidden + (size_t)(m0 + r) * DM + k0 + c4 * 4);
        }
        #pragma unroll
        for (int i = 0; i < 2; i++) {
            int idx = tid + i * 256;
            int j = idx >> 3, c4 = idx & 7;
            cpa16(Bd + j * 36 + c4 * 4, pw + (size_t)(n0 + j) * DM + k0 + c4 * 4);
        }
    };

    loadTile(0, 0); CPCOMMIT;
    loadTile(1, 1); CPCOMMIT;

    for (int it = 0; it < 32; it++) {
        CPWAIT1;
        __syncthreads();
        const float* A_ = As + (it & 1) * (128*36);
        const float* B_ = Bs + (it & 1) * (64*36);
        #pragma unroll
        for (int kk = 0; kk < 4; kk++) {
            unsigned a[2][4];
            #pragma unroll
            for (int mi = 0; mi < 2; mi++) {
                int rb = wm * 32 + mi * 16;
                a[mi][0] = f2tf(A_[(rb + g) * 36 + kk * 8 + tg]);
                a[mi][1] = f2tf(A_[(rb + g + 8) * 36 + kk * 8 + tg]);
                a[mi][2] = f2tf(A_[(rb + g) * 36 + kk * 8 + tg + 4]);
                a[mi][3] = f2tf(A_[(rb + g + 8) * 36 + kk * 8 + tg + 4]);
            }
            #pragma unroll
            for (int ni = 0; ni < 4; ni++) {
                unsigned b0 = __float_as_uint(B_[(wn * 32 + ni * 8 + g) * 36 + kk * 8 + tg]);
                unsigned b1 = __float_as_uint(B_[(wn * 32 + ni * 8 + g) * 36 + kk * 8 + tg + 4]);
                #pragma unroll
                for (int mi = 0; mi < 2; mi++)
                    mma_tf32(c[mi][ni][0], c[mi][ni][1], c[mi][ni][2], c[mi][ni][3],
                             a[mi][0], a[mi][1], a[mi][2], a[mi][3], b0, b1);
            }
        }
        __syncthreads();
        if (it + 2 < 32) loadTile(it & 1, it + 2);
        CPCOMMIT;
    }
    #pragma unroll
    for (int mi = 0; mi < 2; mi++)
        #pragma unroll
        for (int ni = 0; ni < 4; ni++) {
            int row = m0 + wm * 32 + mi * 16 + g;
            int col = n0 + wn * 32 + ni * 8 + 2 * tg;
            float b0v = pb[col], b1v = pb[col + 1];
            g_res[(size_t)row * DM + col]     = c[mi][ni][0] + b0v + qin[(size_t)row * DM + col];
            g_res[(size_t)row * DM + col + 1] = c[mi][ni][1] + b1v + qin[(size_t)row * DM + col + 1];
            g_res[(size_t)(row + 8) * DM + col]     = c[mi][ni][2] + b0v + qin[(size_t)(row + 8) * DM + col];
            g_res[(size_t)(row + 8) * DM + col + 1] = c[mi][ni][3] + b1v + qin[(size_t)(row + 8) * DM + col + 1];
        }
}

// ---------- K4: LayerNorm ----------
__global__ __launch_bounds__(256) void ln_kernel(const float* __restrict__ gma,
                                                 const float* __restrict__ bta,
                                                 float* __restrict__ out)
{
    int r = blockIdx.x, tid = threadIdx.x;
    const float* x = g_res + (size_t)r * DM;
    float4 xv = *(const float4*)(x + tid * 4);
    float s  = xv.x + xv.y + xv.z + xv.w;
    float sq = xv.x * xv.x + xv.y * xv.y + xv.z * xv.z + xv.w * xv.w;
    #pragma unroll
    for (int o = 16; o > 0; o >>= 1) {
        s  += __shfl_xor_sync(0xffffffffu, s, o);
        sq += __shfl_xor_sync(0xffffffffu, sq, o);
    }
    __shared__ float ss[8], ssq[8];
    int w = tid >> 5;
    if ((tid & 31) == 0) { ss[w] = s; ssq[w] = sq; }
    __syncthreads();
    if (tid < 32) {
        s  = (tid < 8) ? ss[tid]  : 0.f;
        sq = (tid < 8) ? ssq[tid] : 0.f;
        #pragma unroll
        for (int o = 4; o > 0; o >>= 1) {
            s  += __shfl_xor_sync(0xffffffffu, s, o);
            sq += __shfl_xor_sync(0xffffffffu, sq, o);
        }
        if (tid == 0) { ss[0] = s; ssq[0] = sq; }
    }
    __syncthreads();
    float mu   = ss[0] * (1.f / 1024.f);
    float var  = ssq[0] * (1.f / 1024.f) - mu * mu;
    float rstd = rsqrtf(var + 1e-6f);
    float4 gv = *(const float4*)(gma + tid * 4);
    float4 bv = *(const float4*)(bta + tid * 4);
    float4 o;
    o.x = (xv.x - mu) * rstd * gv.x + bv.x;
    o.y = (xv.y - mu) * rstd * gv.y + bv.y;
    o.z = (xv.z - mu) * rstd * gv.z + bv.z;
    o.w = (xv.w - mu) * rstd * gv.w + bv.w;
    *(float4*)(out + (size_t)r * DM + tid * 4) = o;
}

extern "C" void kernel_launch(void* const* d_in, const int* in_sizes, int n_in,
                              void* d_out, int out_size) {
    const float* q  = (const float*)d_in[0];
    const float* k  = (const float*)d_in[1];
    const float* v  = (const float*)d_in[2];
    const void*  mk = d_in[3];
    const float* wq = (const float*)d_in[4];
    const float* wk = (const float*)d_in[5];
    const float* wv = (const float*)d_in[6];
    const float* pw = (const float*)d_in[7];
    const float* pb = (const float*)d_in[8];
    const float* lg = (const float*)d_in[9];
    const float* lb = (const float*)d_in[10];
    float* out = (float*)d_out;
    int full = (out_size >= (int)FULL_OUT) ? 1 : 0;

    const int gemm_smem = (2*128*36 + 2*32*72) * 4;   // 55296
    const int pv_smem   = (128*68 + 64*68 + 128) * 4; // 52736
    cudaFuncSetAttribute(qkv_gemm_kernel, cudaFuncAttributeMaxDynamicSharedMemorySize, gemm_smem);
    cudaFuncSetAttribute(proj_gemm_kernel, cudaFuncAttributeMaxDynamicSharedMemorySize, gemm_smem);
    cudaFuncSetAttribute(pv_kernel, cudaFuncAttributeMaxDynamicSharedMemorySize, pv_smem);

    detect_mask_kernel<<<1, 256>>>((const unsigned char*)mk);
    convert_mask_kernel<<<32768, 256>>>(mk);
    dim3 gq(64, 1, 48);
    qkv_gemm_kernel<<<gq, 256, gemm_smem>>>(q, k, v, wq, wk, wv);
    dim3 ga(8, 128);
    score_kernel<<<ga, 256>>>(out);
    pv_kernel<<<ga, 256, pv_smem>>>(out, full);
    dim3 gp(64, 16);
    proj_gemm_kernel<<<gp, 256, gemm_smem>>>(q, pw, pb);
    ln_kernel<<<MROWS, 256>>>(lg, lb, out);
}